// round 1
// baseline (speedup 1.0000x reference)
#include <cuda_runtime.h>

// KPConv fused kernel, fp32 with packed f32x2 FMA (FFMA2).
// inputs (metadata order): q_pts[ N,3 ], s_pts(unused), neighbors[ N,32,3 ],
// neighb_inds(unused), x[ N,32,64 ], kernel_points[ 15,3 ], weights[ 15,64,64 ]
// output: out[ N,64 ] float32

#define KPTS 15
#define NNB  32
#define CIN  64
#define COUT 64
#define PBLK 8
#define THREADS 128

// W repacked as float4: Wp[(k*16+cq)*64 + d] = (W[k][4cq][d], W[k][4cq+1][d], W[k][4cq+2][d], W[k][4cq+3][d])
__device__ float4 g_Wp[KPTS * 16 * COUT];

__device__ __forceinline__ unsigned long long ffma2(unsigned long long a,
                                                    unsigned long long b,
                                                    unsigned long long c) {
    unsigned long long d;
    asm("fma.rn.f32x2 %0, %1, %2, %3;" : "=l"(d) : "l"(a), "l"(b), "l"(c));
    return d;
}
__device__ __forceinline__ unsigned long long pack2(float lo, float hi) {
    unsigned long long r;
    asm("mov.b64 %0, {%1, %2};" : "=l"(r) : "f"(lo), "f"(hi));
    return r;
}
__device__ __forceinline__ float2 unpack2(unsigned long long v) {
    float2 r;
    asm("mov.b64 {%0, %1}, %2;" : "=f"(r.x), "=f"(r.y) : "l"(v));
    return r;
}

__global__ void pack_w_kernel(const float* __restrict__ W) {
    int i = blockIdx.x * blockDim.x + threadIdx.x;
    if (i >= KPTS * 16 * COUT) return;
    int d  = i & 63;
    int cq = (i >> 6) & 15;
    int k  = i >> 10;
    float4 v;
    v.x = W[(k * CIN + 4 * cq + 0) * COUT + d];
    v.y = W[(k * CIN + 4 * cq + 1) * COUT + d];
    v.z = W[(k * CIN + 4 * cq + 2) * COUT + d];
    v.w = W[(k * CIN + 4 * cq + 3) * COUT + d];
    g_Wp[i] = v;
}

__global__ __launch_bounds__(THREADS)
void kpconv_kernel(const float* __restrict__ q_pts,
                   const float* __restrict__ neighbors,
                   const float* __restrict__ x,
                   const float* __restrict__ kernel_points,
                   float* __restrict__ out,
                   int N)
{
    __shared__ float w_sh[PBLK * KPTS * NNB];    // 15360 B
    __shared__ float wt_sh[PBLK * KPTS * CIN];   // 30720 B
    __shared__ float kp_sh[KPTS * 3];

    const int tid  = threadIdx.x;
    const int base = blockIdx.x * PBLK;

    if (tid < KPTS * 3) kp_sh[tid] = kernel_points[tid];
    __syncthreads();

    // ---- Phase 1: kernel-point influence weights w[p][k][m] ----
    const float inv_ext = 1.0f / 0.06f;
    for (int s = tid; s < PBLK * NNB; s += THREADS) {
        int p = s >> 5;
        int m = s & 31;
        int np = base + p; if (np >= N) np = N - 1;
        float qx = q_pts[np * 3 + 0];
        float qy = q_pts[np * 3 + 1];
        float qz = q_pts[np * 3 + 2];
        int nb = (np * NNB + m) * 3;
        float rx = neighbors[nb + 0] - qx;
        float ry = neighbors[nb + 1] - qy;
        float rz = neighbors[nb + 2] - qz;
        #pragma unroll
        for (int k = 0; k < KPTS; k++) {
            float dx = rx - kp_sh[k * 3 + 0];
            float dy = ry - kp_sh[k * 3 + 1];
            float dz = rz - kp_sh[k * 3 + 2];
            float sq = dx * dx + dy * dy + dz * dz;
            float w  = fmaxf(1.0f - sqrtf(sq) * inv_ext, 0.0f);
            w_sh[(p * KPTS + k) * NNB + m] = w;
        }
    }
    __syncthreads();

    // ---- Phase 2: weighted[p][k][c] = sum_m w[p][k][m] * x[np][m][c] ----
    {
        const int c = tid & 63;
        #pragma unroll 1
        for (int pass = 0; pass < PBLK / 2; pass++) {
            int p = pass * 2 + (tid >> 6);
            int np = base + p; if (np >= N) np = N - 1;
            const float* xp = x + (np * NNB) * CIN + c;
            float xs[NNB];
            #pragma unroll
            for (int m = 0; m < NNB; m++) xs[m] = __ldg(xp + m * CIN);
            unsigned long long x2[NNB / 2];
            #pragma unroll
            for (int j = 0; j < NNB / 2; j++) x2[j] = pack2(xs[2 * j], xs[2 * j + 1]);
            #pragma unroll
            for (int k = 0; k < KPTS; k++) {
                unsigned long long aa = 0ull, ab = 0ull;
                const ulonglong2* wrow =
                    (const ulonglong2*)&w_sh[(p * KPTS + k) * NNB];
                #pragma unroll
                for (int j = 0; j < 8; j++) {
                    ulonglong2 w4 = wrow[j];   // 4 consecutive w values (2 pairs), LDS.128 broadcast
                    aa = ffma2(w4.x, x2[2 * j + 0], aa);
                    ab = ffma2(w4.y, x2[2 * j + 1], ab);
                }
                float2 fa = unpack2(aa), fb = unpack2(ab);
                wt_sh[(p * KPTS + k) * CIN + c] = (fa.x + fa.y) + (fb.x + fb.y);
            }
        }
    }
    __syncthreads();

    // ---- Phase 3: out[np][d] = sum_{k,c} weighted[p][k][c] * W[k][c][d] ----
    {
        const int d    = tid & 63;
        const int half = tid >> 6;           // 2 halves x 4 points each
        unsigned long long aa[4] = {0ull, 0ull, 0ull, 0ull};
        unsigned long long ab[4] = {0ull, 0ull, 0ull, 0ull};
        const ulonglong2* Wp = (const ulonglong2*)g_Wp;
        #pragma unroll 1
        for (int k = 0; k < KPTS; k++) {
            #pragma unroll
            for (int cq = 0; cq < 16; cq++) {
                ulonglong2 Wv = __ldg(Wp + ((k * 16 + cq) * COUT + d)); // LDG.128 coalesced
                #pragma unroll
                for (int j = 0; j < 4; j++) {
                    int p = half * 4 + j;
                    ulonglong2 wt4 = *(const ulonglong2*)
                        &wt_sh[(p * KPTS + k) * CIN + 4 * cq];          // LDS.128 broadcast
                    aa[j] = ffma2(wt4.x, Wv.x, aa[j]);
                    ab[j] = ffma2(wt4.y, Wv.y, ab[j]);
                }
            }
        }
        #pragma unroll
        for (int j = 0; j < 4; j++) {
            int np = base + half * 4 + j;
            if (np < N) {
                float2 fa = unpack2(aa[j]), fb = unpack2(ab[j]);
                out[np * COUT + d] = (fa.x + fa.y) + (fb.x + fb.y);
            }
        }
    }
}

extern "C" void kernel_launch(void* const* d_in, const int* in_sizes, int n_in,
                              void* d_out, int out_size) {
    const float* q_pts = (const float*)d_in[0];
    // d_in[1] = s_pts (unused by reference)
    const float* neighbors = (const float*)d_in[2];
    // d_in[3] = neighb_inds (unused by reference)
    const float* x  = (const float*)d_in[4];
    const float* kp = (const float*)d_in[5];
    const float* W  = (const float*)d_in[6];
    float* out = (float*)d_out;

    int N = in_sizes[0] / 3;

    pack_w_kernel<<<(KPTS * 16 * COUT + 255) / 256, 256>>>(W);
    int grid = (N + PBLK - 1) / PBLK;
    kpconv_kernel<<<grid, THREADS>>>(q_pts, neighbors, x, kp, out, N);
}

// round 2
// speedup vs baseline: 1.5779x; 1.5779x over previous
#include <cuda_runtime.h>

// KPConv fused, fp32, packed f32x2 FMA (FFMA2), L1-op-minimized blocking.
// inputs: q_pts[N,3], s_pts(unused), neighbors[N,32,3], neighb_inds(unused),
//         x[N,32,64], kernel_points[15,3], weights[15,64,64]
// output: out[N,64] float32

#define KPTS 15
#define NNB  32
#define CIN  64
#define COUT 64
#define PBLK 8
#define THREADS 128

// W repacked: Wp[(k*16+cq)*64 + d] = float4(W[k][4cq+0][d], W[k][4cq+1][d], W[k][4cq+2][d], W[k][4cq+3][d])
__device__ float4 g_Wp[KPTS * 16 * COUT];

__device__ __forceinline__ unsigned long long ffma2(unsigned long long a,
                                                    unsigned long long b,
                                                    unsigned long long c) {
    unsigned long long d;
    asm("fma.rn.f32x2 %0, %1, %2, %3;" : "=l"(d) : "l"(a), "l"(b), "l"(c));
    return d;
}
__device__ __forceinline__ unsigned long long pack2(float lo, float hi) {
    unsigned long long r;
    asm("mov.b64 %0, {%1, %2};" : "=l"(r) : "f"(lo), "f"(hi));
    return r;
}
__device__ __forceinline__ float hsum2(unsigned long long v) {
    float lo, hi;
    asm("mov.b64 {%0, %1}, %2;" : "=f"(lo), "=f"(hi) : "l"(v));
    return lo + hi;
}

__global__ void pack_w_kernel(const float* __restrict__ W) {
    int i = blockIdx.x * blockDim.x + threadIdx.x;
    if (i >= KPTS * 16 * COUT) return;
    int d  = i & 63;
    int cq = (i >> 6) & 15;
    int k  = i >> 10;
    float4 v;
    v.x = W[(k * CIN + 4 * cq + 0) * COUT + d];
    v.y = W[(k * CIN + 4 * cq + 1) * COUT + d];
    v.z = W[(k * CIN + 4 * cq + 2) * COUT + d];
    v.w = W[(k * CIN + 4 * cq + 3) * COUT + d];
    g_Wp[i] = v;
}

__global__ __launch_bounds__(THREADS, 4)
void kpconv_kernel(const float* __restrict__ q_pts,
                   const float* __restrict__ neighbors,
                   const float* __restrict__ x,
                   const float* __restrict__ kernel_points,
                   float* __restrict__ out,
                   int N)
{
    __shared__ float wt_sh[PBLK * KPTS * CIN];   // 30720 B
    __shared__ float w_sh[PBLK * KPTS * NNB];    // 15360 B (aliased as reduction buf later)
    __shared__ float kp_sh[KPTS * 3];

    const int tid  = threadIdx.x;
    const int base = blockIdx.x * PBLK;

    if (tid < KPTS * 3) kp_sh[tid] = kernel_points[tid];
    __syncthreads();

    // ---- Phase 1: influence weights w[p][k][m] ----
    const float inv_ext = 1.0f / 0.06f;
    #pragma unroll
    for (int s = tid; s < PBLK * NNB; s += THREADS) {
        int p = s >> 5;
        int m = s & 31;
        int np = base + p; if (np >= N) np = N - 1;
        float qx = q_pts[np * 3 + 0];
        float qy = q_pts[np * 3 + 1];
        float qz = q_pts[np * 3 + 2];
        int nb = (np * NNB + m) * 3;
        float rx = neighbors[nb + 0] - qx;
        float ry = neighbors[nb + 1] - qy;
        float rz = neighbors[nb + 2] - qz;
        #pragma unroll
        for (int k = 0; k < KPTS; k++) {
            float dx = rx - kp_sh[k * 3 + 0];
            float dy = ry - kp_sh[k * 3 + 1];
            float dz = rz - kp_sh[k * 3 + 2];
            float sq = dx * dx + dy * dy + dz * dz;
            w_sh[(p * KPTS + k) * NNB + m] = fmaxf(1.0f - sqrtf(sq) * inv_ext, 0.0f);
        }
    }
    __syncthreads();

    // ---- Phase 2: wt[p][k][c] = sum_m w[p][k][m] * x[np][m][c]  (2-c blocking) ----
    {
        const int c0 = tid & 31;        // lane: c0 and c0+32
        const int pg = tid >> 5;        // warp -> 2 points
        #pragma unroll 1
        for (int pi = 0; pi < 2; pi++) {
            int p = pg * 2 + pi;
            int np = base + p; if (np >= N) np = N - 1;
            const float* xp = x + (long long)np * NNB * CIN;
            unsigned long long xa[NNB / 2], xb[NNB / 2];
            #pragma unroll
            for (int j = 0; j < NNB / 2; j++) {
                float a0 = __ldg(xp + (2 * j) * CIN + c0);
                float a1 = __ldg(xp + (2 * j + 1) * CIN + c0);
                xa[j] = pack2(a0, a1);
                float b0 = __ldg(xp + (2 * j) * CIN + c0 + 32);
                float b1 = __ldg(xp + (2 * j + 1) * CIN + c0 + 32);
                xb[j] = pack2(b0, b1);
            }
            #pragma unroll
            for (int k = 0; k < KPTS; k++) {
                const ulonglong2* wrow = (const ulonglong2*)&w_sh[(p * KPTS + k) * NNB];
                unsigned long long aa = 0ull, ab = 0ull, ba = 0ull, bb = 0ull;
                #pragma unroll
                for (int j = 0; j < 8; j++) {
                    ulonglong2 w4 = wrow[j];            // 4 w's (2 f32x2), warp-broadcast
                    aa = ffma2(w4.x, xa[2 * j + 0], aa);
                    ab = ffma2(w4.y, xa[2 * j + 1], ab);
                    ba = ffma2(w4.x, xb[2 * j + 0], ba);
                    bb = ffma2(w4.y, xb[2 * j + 1], bb);
                }
                wt_sh[(p * KPTS + k) * CIN + c0]      = hsum2(aa) + hsum2(ab);
                wt_sh[(p * KPTS + k) * CIN + c0 + 32] = hsum2(ba) + hsum2(bb);
            }
        }
    }
    __syncthreads();

    // ---- Phase 3: out[p][d] = sum_{k,c} wt[p][k][c] * W[k][c][d] ----
    // warps = c-quarters (4-way split), lanes = d0, D=2 (d0, d0+32), P=8.
    {
        const int d0 = tid & 31;
        const int cw = tid >> 5;                 // c-quarter
        unsigned long long acc[PBLK][2];
        #pragma unroll
        for (int p = 0; p < PBLK; p++) { acc[p][0] = 0ull; acc[p][1] = 0ull; }

        const ulonglong2* Wp = (const ulonglong2*)g_Wp;
        #pragma unroll 1
        for (int k = 0; k < KPTS; k++) {
            #pragma unroll
            for (int cq = 0; cq < 4; cq++) {
                int cquad = cw * 4 + cq;                         // 0..15
                long long widx = (long long)(k * 16 + cquad) * COUT;
                ulonglong2 Wv0 = __ldg(Wp + widx + d0);          // LDG.128
                ulonglong2 Wv1 = __ldg(Wp + widx + d0 + 32);     // LDG.128
                #pragma unroll
                for (int p = 0; p < PBLK; p++) {
                    ulonglong2 wt4 = *(const ulonglong2*)
                        &wt_sh[(p * KPTS + k) * CIN + cquad * 4]; // LDS.128 broadcast
                    acc[p][0] = ffma2(wt4.x, Wv0.x, acc[p][0]);
                    acc[p][0] = ffma2(wt4.y, Wv0.y, acc[p][0]);
                    acc[p][1] = ffma2(wt4.x, Wv1.x, acc[p][1]);
                    acc[p][1] = ffma2(wt4.y, Wv1.y, acc[p][1]);
                }
            }
        }

        // ---- cross-c-quarter reduction via smem (aliased over w_sh) ----
        float* red = w_sh;                       // needs 4*8*64*4 = 8192 B <= 15360 B
        __syncthreads();                         // all warps done reading w_sh (phase 2)
        #pragma unroll
        for (int p = 0; p < PBLK; p++) {
            red[(cw * PBLK + p) * COUT + d0]      = hsum2(acc[p][0]);
            red[(cw * PBLK + p) * COUT + d0 + 32] = hsum2(acc[p][1]);
        }
        __syncthreads();
        #pragma unroll
        for (int j = 0; j < 4; j++) {
            int o = j * THREADS + tid;           // 0..511
            int p = o >> 6;
            int d = o & 63;
            int np = base + p;
            if (np < N) {
                float v = red[(0 * PBLK + p) * COUT + d]
                        + red[(1 * PBLK + p) * COUT + d]
                        + red[(2 * PBLK + p) * COUT + d]
                        + red[(3 * PBLK + p) * COUT + d];
                out[(long long)np * COUT + d] = v;
            }
        }
    }
}

extern "C" void kernel_launch(void* const* d_in, const int* in_sizes, int n_in,
                              void* d_out, int out_size) {
    const float* q_pts = (const float*)d_in[0];
    const float* neighbors = (const float*)d_in[2];
    const float* x  = (const float*)d_in[4];
    const float* kp = (const float*)d_in[5];
    const float* W  = (const float*)d_in[6];
    float* out = (float*)d_out;

    int N = in_sizes[0] / 3;

    pack_w_kernel<<<(KPTS * 16 * COUT + 255) / 256, 256>>>(W);
    int grid = (N + PBLK - 1) / PBLK;
    kpconv_kernel<<<grid, THREADS>>>(q_pts, neighbors, x, kp, out, N);
}

// round 4
// speedup vs baseline: 1.8794x; 1.1911x over previous
#include <cuda_runtime.h>
#include <cuda_fp16.h>
#include <cstdint>

// KPConv fused: phase1/2 fp32 FFMA2, phase3 = HMMA (mma.sync m16n8k16 fp16).
// inputs: q_pts[N,3], s_pts(unused), neighbors[N,32,3], neighb_inds(unused),
//         x[N,32,64], kernel_points[15,3], weights[15,64,64] -> out[N,64] f32
//
// Per block (512 thr, 32 points): out[32][64] = wt[32][960] @ W[960][64]
//  A = wt fp16 smem, rows=pts, 120 16B-chunks/row, chunk swizzled ^(row&7)
//  B = W fp16 pre-packed in gmem in mma B-fragment layout (coalesced LDG.64)
//  16 warps = (kh 2) x (mt 2) x (ng 4); K-half partials reduced via smem.

#define KPTS 15
#define NNB  32
#define CIN  64
#define COUT 64
#define PBLK 32
#define THREADS 512
#define NKS  60                 // 960 / 16
#define ROWB 1920               // wt row stride bytes (960 * 2)
#define WT_BYTES (PBLK * ROWB)  // 61440
#define W_BYTES  (PBLK * KPTS * NNB * 4)  // 61440
#define SMEM_TOTAL (WT_BYTES + W_BYTES + 1024)

typedef unsigned long long ull;

// B fragments: [nt(8)][ks(60)][lane(32)] -> uint2 {b0(2 f16), b1(2 f16)}
__device__ uint2 g_Bfrag[8 * NKS * 32];

static __device__ __forceinline__ uint32_t smem_u32(const void* p) {
    uint32_t a;
    asm("{ .reg .u64 t; cvta.to.shared.u64 t, %1; cvt.u32.u64 %0, t; }" : "=r"(a) : "l"(p));
    return a;
}
static __device__ __forceinline__ ull ffma2(ull a, ull b, ull c) {
    ull d; asm("fma.rn.f32x2 %0, %1, %2, %3;" : "=l"(d) : "l"(a), "l"(b), "l"(c)); return d;
}
static __device__ __forceinline__ ull pack2(float lo, float hi) {
    ull r; asm("mov.b64 %0, {%1, %2};" : "=l"(r) : "f"(lo), "f"(hi)); return r;
}
static __device__ __forceinline__ float hsum2(ull v) {
    float lo, hi; asm("mov.b64 {%0, %1}, %2;" : "=f"(lo), "=f"(hi) : "l"(v)); return lo + hi;
}
static __device__ __forceinline__ void ldm_x4(uint32_t& a0, uint32_t& a1,
                                              uint32_t& a2, uint32_t& a3, uint32_t addr) {
    asm volatile("ldmatrix.sync.aligned.m8n8.x4.shared.b16 {%0,%1,%2,%3}, [%4];"
                 : "=r"(a0), "=r"(a1), "=r"(a2), "=r"(a3) : "r"(addr));
}
static __device__ __forceinline__ void mma16816(float* c, uint32_t a0, uint32_t a1,
                                                uint32_t a2, uint32_t a3,
                                                uint32_t b0, uint32_t b1) {
    asm volatile("mma.sync.aligned.m16n8k16.row.col.f32.f16.f16.f32 "
                 "{%0,%1,%2,%3}, {%4,%5,%6,%7}, {%8,%9}, {%0,%1,%2,%3};"
                 : "+f"(c[0]), "+f"(c[1]), "+f"(c[2]), "+f"(c[3])
                 : "r"(a0), "r"(a1), "r"(a2), "r"(a3), "r"(b0), "r"(b1));
}

// Pack W[j=kpt*64+c][d] (row-major j x 64) into per-thread B fragments.
// m16n8k16 B frag: thread t: b0 = (k=(t%4)*2 +{0,1}, n=t/4), b1 = same k+8.
__global__ void pack_bfrag(const float* __restrict__ W) {
    int i = blockIdx.x * blockDim.x + threadIdx.x;
    if (i >= 8 * NKS * 32) return;
    int lane = i & 31;
    int ks   = (i >> 5) % NKS;
    int nt   = i / (NKS * 32);
    int n  = nt * 8 + (lane >> 2);
    int j0 = ks * 16 + (lane & 3) * 2;
    __half2 b0 = __floats2half2_rn(W[(j0 + 0) * COUT + n], W[(j0 + 1) * COUT + n]);
    __half2 b1 = __floats2half2_rn(W[(j0 + 8) * COUT + n], W[(j0 + 9) * COUT + n]);
    uint2 v;
    v.x = *(const uint32_t*)&b0;
    v.y = *(const uint32_t*)&b1;
    g_Bfrag[i] = v;
}

__global__ __launch_bounds__(THREADS, 1)
void kpconv_kernel(const float* __restrict__ q_pts,
                   const float* __restrict__ neighbors,
                   const float* __restrict__ x,
                   const float* __restrict__ kernel_points,
                   float* __restrict__ out,
                   int N)
{
    extern __shared__ char smem_raw[];
    char* smem = (char*)(((uintptr_t)smem_raw + 1023) & ~(uintptr_t)1023);
    char*  wt_sh = smem;                         // fp16 A tile, swizzled
    float* w_sh  = (float*)(smem + WT_BYTES);    // fp32 influence weights (aliased by red)
    __shared__ float kp_sh[KPTS * 3];
    const uint32_t wt_u32 = smem_u32(wt_sh);

    const int tid  = threadIdx.x;
    const int wid  = tid >> 5;
    const int lane = tid & 31;
    const int base = blockIdx.x * PBLK;

    if (tid < KPTS * 3) kp_sh[tid] = kernel_points[tid];
    __syncthreads();

    // ---- Phase 1: w[p][k][m] ----
    const float inv_ext = 1.0f / 0.06f;
    #pragma unroll
    for (int s = tid; s < PBLK * NNB; s += THREADS) {
        int p = s >> 5, m = s & 31;
        int np = base + p; if (np >= N) np = N - 1;
        float qx = q_pts[np * 3 + 0];
        float qy = q_pts[np * 3 + 1];
        float qz = q_pts[np * 3 + 2];
        int nb = (np * NNB + m) * 3;
        float rx = neighbors[nb + 0] - qx;
        float ry = neighbors[nb + 1] - qy;
        float rz = neighbors[nb + 2] - qz;
        #pragma unroll
        for (int k = 0; k < KPTS; k++) {
            float dx = rx - kp_sh[k * 3 + 0];
            float dy = ry - kp_sh[k * 3 + 1];
            float dz = rz - kp_sh[k * 3 + 2];
            float sq = dx * dx + dy * dy + dz * dz;
            w_sh[(p * KPTS + k) * NNB + m] = fmaxf(1.0f - sqrtf(sq) * inv_ext, 0.0f);
        }
    }
    __syncthreads();

    // ---- Phase 2: wt[p][j=k*64+c] fp16 -> swizzled A tile ----
    // warp = 2 points, lane = c0 (and c0+32).
    {
        #pragma unroll 1
        for (int pi = 0; pi < 2; pi++) {
            int p = wid * 2 + pi;
            int np = base + p; if (np >= N) np = N - 1;
            const float* xp = x + (long long)np * NNB * CIN;
            ull xa[NNB / 2], xb[NNB / 2];
            #pragma unroll
            for (int j = 0; j < NNB / 2; j++) {
                xa[j] = pack2(__ldg(xp + (2 * j) * CIN + lane),
                              __ldg(xp + (2 * j + 1) * CIN + lane));
                xb[j] = pack2(__ldg(xp + (2 * j) * CIN + lane + 32),
                              __ldg(xp + (2 * j + 1) * CIN + lane + 32));
            }
            char* row = wt_sh + p * ROWB;
            int   sw  = p & 7;
            #pragma unroll
            for (int k = 0; k < KPTS; k++) {
                const ulonglong2* wrow = (const ulonglong2*)&w_sh[(p * KPTS + k) * NNB];
                ull aa = 0, ab = 0, ba = 0, bb = 0;
                #pragma unroll
                for (int j = 0; j < 8; j++) {
                    ulonglong2 w4 = wrow[j];
                    aa = ffma2(w4.x, xa[2 * j + 0], aa);
                    ab = ffma2(w4.y, xa[2 * j + 1], ab);
                    ba = ffma2(w4.x, xb[2 * j + 0], ba);
                    bb = ffma2(w4.y, xb[2 * j + 1], bb);
                }
                float va = hsum2(aa) + hsum2(ab);     // j = k*64 + lane
                float vb = hsum2(ba) + hsum2(bb);     // j = k*64 + lane + 32
                int ch1 = (k * 8 + (lane >> 3)) ^ sw;
                int ch2 = (k * 8 + 4 + (lane >> 3)) ^ sw;
                *(__half*)(row + (ch1 << 4) + (lane & 7) * 2) = __float2half_rn(va);
                *(__half*)(row + (ch2 << 4) + (lane & 7) * 2) = __float2half_rn(vb);
            }
        }
    }
    __syncthreads();

    // ---- Phase 3: HMMA GEMM out[32][64] = wt @ W ----
    // warp: kh = wid>>3, mt = (wid>>2)&1, ng = wid&3
    {
        const int kh = wid >> 3;
        const int mt = (wid >> 2) & 1;
        const int ng = wid & 3;
        const int rowA = mt * 16 + (lane & 15);
        const uint32_t a_row = wt_u32 + rowA * ROWB;
        const int swA = rowA & 7;
        const int khalf = lane >> 4;

        float c0[4] = {0.f, 0.f, 0.f, 0.f};
        float c1[4] = {0.f, 0.f, 0.f, 0.f};
        const uint2* Bf0 = g_Bfrag + ((ng * 2 + 0) * NKS) * 32 + lane;
        const uint2* Bf1 = g_Bfrag + ((ng * 2 + 1) * NKS) * 32 + lane;

        #pragma unroll 5
        for (int s = 0; s < NKS / 2; s++) {
            int ks = kh * (NKS / 2) + s;
            uint32_t addr = a_row + ((((ks << 1) + khalf) ^ swA) << 4);
            uint32_t a0, a1, a2, a3;
            ldm_x4(a0, a1, a2, a3, addr);
            uint2 b0 = __ldg(Bf0 + ks * 32);
            uint2 b1 = __ldg(Bf1 + ks * 32);
            mma16816(c0, a0, a1, a2, a3, b0.x, b0.y);
            mma16816(c1, a0, a1, a2, a3, b1.x, b1.y);
        }

        // ---- reduce across K-halves via smem (alias over w_sh) ----
        float* red = w_sh;                  // 16*32*4*4 = 8192 B
        __syncthreads();                    // w_sh no longer needed
        if (kh == 1) {
            int rw = wid & 7;
            #pragma unroll
            for (int r = 0; r < 4; r++) {
                red[((rw * 2 + 0) * 32 + lane) * 4 + r] = c0[r];
                red[((rw * 2 + 1) * 32 + lane) * 4 + r] = c1[r];
            }
        }
        __syncthreads();
        if (kh == 0) {
            int rw = wid & 7;
            #pragma unroll
            for (int r = 0; r < 4; r++) {
                c0[r] += red[((rw * 2 + 0) * 32 + lane) * 4 + r];
                c1[r] += red[((rw * 2 + 1) * 32 + lane) * 4 + r];
            }
            int r0 = base + mt * 16 + (lane >> 2);
            int r1 = r0 + 8;
            int col0 = (ng * 2 + 0) * 8 + (lane & 3) * 2;
            int col1 = (ng * 2 + 1) * 8 + (lane & 3) * 2;
            if (r0 < N) {
                *(float2*)&out[(long long)r0 * COUT + col0] = make_float2(c0[0], c0[1]);
                *(float2*)&out[(long long)r0 * COUT + col1] = make_float2(c1[0], c1[1]);
            }
            if (r1 < N) {
                *(float2*)&out[(long long)r1 * COUT + col0] = make_float2(c0[2], c0[3]);
                *(float2*)&out[(long long)r1 * COUT + col1] = make_float2(c1[2], c1[3]);
            }
        }
    }
}

extern "C" void kernel_launch(void* const* d_in, const int* in_sizes, int n_in,
                              void* d_out, int out_size) {
    const float* q_pts     = (const float*)d_in[0];
    const float* neighbors = (const float*)d_in[2];
    const float* x         = (const float*)d_in[4];
    const float* kp        = (const float*)d_in[5];
    const float* W         = (const float*)d_in[6];
    float* out = (float*)d_out;

    int N = in_sizes[0] / 3;

    cudaFuncSetAttribute(kpconv_kernel,
                         cudaFuncAttributeMaxDynamicSharedMemorySize, SMEM_TOTAL);

    pack_bfrag<<<(8 * NKS * 32 + 255) / 256, 256>>>(W);
    int grid = (N + PBLK - 1) / PBLK;
    kpconv_kernel<<<grid, THREADS, SMEM_TOTAL>>>(q_pts, neighbors, x, kp, out, N);
}

// round 5
// speedup vs baseline: 2.0864x; 1.1101x over previous
#include <cuda_runtime.h>
#include <cuda_fp16.h>
#include <cstdint>

// KPConv fused: phase1/2 fp32 FFMA2 (m-split, reg-capped), phase3 HMMA m16n8k16.
// 2 CTAs/SM: 512 thr, <=64 regs, ~92KB smem.
// inputs: q_pts[N,3], s_pts(unused), neighbors[N,32,3], neighb_inds(unused),
//         x[N,32,64], kernel_points[15,3], weights[15,64,64] -> out[N,64] f32

#define KPTS 15
#define NNB  32
#define CIN  64
#define COUT 64
#define PBLK 32
#define HALF_PTS 16
#define THREADS 512
#define NKS  60                  // 960 / 16
#define ROWB 1920                // wt row stride bytes (960 * 2)
#define WT_BYTES (PBLK * ROWB)   // 61440
#define WSH_BYTES (HALF_PTS * KPTS * NNB * 4)   // 30720
#define SMEM_TOTAL (WT_BYTES + WSH_BYTES + 1024)

typedef unsigned long long ull;

// B fragments: [nt(8)][ks(60)][lane(32)] -> uint2 {b0, b1}
__device__ uint2 g_Bfrag[8 * NKS * 32];

static __device__ __forceinline__ uint32_t smem_u32(const void* p) {
    uint32_t a;
    asm("{ .reg .u64 t; cvta.to.shared.u64 t, %1; cvt.u32.u64 %0, t; }" : "=r"(a) : "l"(p));
    return a;
}
static __device__ __forceinline__ ull ffma2(ull a, ull b, ull c) {
    ull d; asm("fma.rn.f32x2 %0, %1, %2, %3;" : "=l"(d) : "l"(a), "l"(b), "l"(c)); return d;
}
static __device__ __forceinline__ ull pack2(float lo, float hi) {
    ull r; asm("mov.b64 %0, {%1, %2};" : "=l"(r) : "f"(lo), "f"(hi)); return r;
}
static __device__ __forceinline__ float hsum2(ull v) {
    float lo, hi; asm("mov.b64 {%0, %1}, %2;" : "=f"(lo), "=f"(hi) : "l"(v)); return lo + hi;
}
static __device__ __forceinline__ void ldm_x4(uint32_t& a0, uint32_t& a1,
                                              uint32_t& a2, uint32_t& a3, uint32_t addr) {
    asm volatile("ldmatrix.sync.aligned.m8n8.x4.shared.b16 {%0,%1,%2,%3}, [%4];"
                 : "=r"(a0), "=r"(a1), "=r"(a2), "=r"(a3) : "r"(addr));
}
static __device__ __forceinline__ void mma16816(float* c, uint32_t a0, uint32_t a1,
                                                uint32_t a2, uint32_t a3,
                                                uint32_t b0, uint32_t b1) {
    asm volatile("mma.sync.aligned.m16n8k16.row.col.f32.f16.f16.f32 "
                 "{%0,%1,%2,%3}, {%4,%5,%6,%7}, {%8,%9}, {%0,%1,%2,%3};"
                 : "+f"(c[0]), "+f"(c[1]), "+f"(c[2]), "+f"(c[3])
                 : "r"(a0), "r"(a1), "r"(a2), "r"(a3), "r"(b0), "r"(b1));
}

__global__ void pack_bfrag(const float* __restrict__ W) {
    int i = blockIdx.x * blockDim.x + threadIdx.x;
    if (i >= 8 * NKS * 32) return;
    int lane = i & 31;
    int ks   = (i >> 5) % NKS;
    int nt   = i / (NKS * 32);
    int n  = nt * 8 + (lane >> 2);
    int j0 = ks * 16 + (lane & 3) * 2;
    __half2 b0 = __floats2half2_rn(W[(j0 + 0) * COUT + n], W[(j0 + 1) * COUT + n]);
    __half2 b1 = __floats2half2_rn(W[(j0 + 8) * COUT + n], W[(j0 + 9) * COUT + n]);
    uint2 v;
    v.x = *(const uint32_t*)&b0;
    v.y = *(const uint32_t*)&b1;
    g_Bfrag[i] = v;
}

__global__ __launch_bounds__(THREADS, 2)
void kpconv_kernel(const float* __restrict__ q_pts,
                   const float* __restrict__ neighbors,
                   const float* __restrict__ x,
                   const float* __restrict__ kernel_points,
                   float* __restrict__ out,
                   int N)
{
    extern __shared__ char smem_raw[];
    char* smem = (char*)(((uintptr_t)smem_raw + 1023) & ~(uintptr_t)1023);
    char*  wt_sh = smem;                         // fp16 A tile (32 rows), swizzled
    float* w_sh  = (float*)(smem + WT_BYTES);    // fp32 influence weights, 16 pts
    __shared__ float kp_sh[KPTS * 3];
    const uint32_t wt_u32 = smem_u32(wt_sh);

    const int tid  = threadIdx.x;
    const int wid  = tid >> 5;
    const int lane = tid & 31;
    const int base = blockIdx.x * PBLK;

    if (tid < KPTS * 3) kp_sh[tid] = kernel_points[tid];
    __syncthreads();

    const float inv_ext = 1.0f / 0.06f;

    // ---- Phase 1+2 in two half-batches of 16 points ----
    #pragma unroll 1
    for (int h = 0; h < 2; h++) {
        // Phase 1: w[p][k][m], 16*32 = 512 items, one per thread
        {
            int p = tid >> 5, m = tid & 31;            // p local 0..15
            int np = base + h * HALF_PTS + p; if (np >= N) np = N - 1;
            float qx = q_pts[np * 3 + 0];
            float qy = q_pts[np * 3 + 1];
            float qz = q_pts[np * 3 + 2];
            int nb = (np * NNB + m) * 3;
            float rx = neighbors[nb + 0] - qx;
            float ry = neighbors[nb + 1] - qy;
            float rz = neighbors[nb + 2] - qz;
            #pragma unroll
            for (int k = 0; k < KPTS; k++) {
                float dx = rx - kp_sh[k * 3 + 0];
                float dy = ry - kp_sh[k * 3 + 1];
                float dz = rz - kp_sh[k * 3 + 2];
                float sq = dx * dx + dy * dy + dz * dz;
                w_sh[(p * KPTS + k) * NNB + m] = fmaxf(1.0f - sqrtf(sq) * inv_ext, 0.0f);
            }
        }
        __syncthreads();

        // Phase 2: warp wid handles local point wid; m split in 2 halves of 16.
        {
            const int p = wid;                         // 0..15 local
            const int gp = h * HALF_PTS + p;           // global row 0..31
            int np = base + gp; if (np >= N) np = N - 1;
            const float* xp = x + (long long)np * NNB * CIN;
            char* row = wt_sh + gp * ROWB;
            const int sw = gp & 7;
            #pragma unroll 1
            for (int mh = 0; mh < 2; mh++) {
                ull xa[8], xb[8];
                #pragma unroll
                for (int j = 0; j < 8; j++) {
                    int m = mh * 16 + 2 * j;
                    xa[j] = pack2(__ldg(xp + m * CIN + lane),
                                  __ldg(xp + (m + 1) * CIN + lane));
                    xb[j] = pack2(__ldg(xp + m * CIN + lane + 32),
                                  __ldg(xp + (m + 1) * CIN + lane + 32));
                }
                #pragma unroll
                for (int k = 0; k < KPTS; k++) {
                    const ulonglong2* wrow =
                        (const ulonglong2*)&w_sh[(p * KPTS + k) * NNB + mh * 16];
                    ull aa = 0, ab = 0, ba = 0, bb = 0;
                    #pragma unroll
                    for (int j = 0; j < 4; j++) {
                        ulonglong2 w4 = wrow[j];
                        aa = ffma2(w4.x, xa[2 * j + 0], aa);
                        ab = ffma2(w4.y, xa[2 * j + 1], ab);
                        ba = ffma2(w4.x, xb[2 * j + 0], ba);
                        bb = ffma2(w4.y, xb[2 * j + 1], bb);
                    }
                    float va = hsum2(aa) + hsum2(ab);
                    float vb = hsum2(ba) + hsum2(bb);
                    int ch1 = (k * 8 + (lane >> 3)) ^ sw;
                    int ch2 = (k * 8 + 4 + (lane >> 3)) ^ sw;
                    __half* s1 = (__half*)(row + (ch1 << 4) + (lane & 7) * 2);
                    __half* s2 = (__half*)(row + (ch2 << 4) + (lane & 7) * 2);
                    if (mh) {                   // accumulate partial from mh=0
                        va += __half2float(*s1);
                        vb += __half2float(*s2);
                    }
                    *s1 = __float2half_rn(va);
                    *s2 = __float2half_rn(vb);
                }
            }
        }
        __syncthreads();
    }

    // ---- Phase 3: HMMA GEMM out[32][64] = wt @ W ----
    {
        const int kh = wid >> 3;
        const int mt = (wid >> 2) & 1;
        const int ng = wid & 3;
        const int rowA = mt * 16 + (lane & 15);
        const uint32_t a_row = wt_u32 + rowA * ROWB;
        const int swA = rowA & 7;
        const int khalf = lane >> 4;

        float c0[4] = {0.f, 0.f, 0.f, 0.f};
        float c1[4] = {0.f, 0.f, 0.f, 0.f};
        const uint2* Bf0 = g_Bfrag + ((ng * 2 + 0) * NKS) * 32 + lane;
        const uint2* Bf1 = g_Bfrag + ((ng * 2 + 1) * NKS) * 32 + lane;

        #pragma unroll 5
        for (int s = 0; s < NKS / 2; s++) {
            int ks = kh * (NKS / 2) + s;
            uint32_t addr = a_row + ((((ks << 1) + khalf) ^ swA) << 4);
            uint32_t a0, a1, a2, a3;
            ldm_x4(a0, a1, a2, a3, addr);
            uint2 b0 = __ldg(Bf0 + ks * 32);
            uint2 b1 = __ldg(Bf1 + ks * 32);
            mma16816(c0, a0, a1, a2, a3, b0.x, b0.y);
            mma16816(c1, a0, a1, a2, a3, b1.x, b1.y);
        }

        // reduce across K-halves via smem (alias over w_sh)
        float* red = w_sh;                  // 8*2*32*4*4 = 8192 B <= 30720
        __syncthreads();
        if (kh == 1) {
            int rw = wid & 7;
            #pragma unroll
            for (int r = 0; r < 4; r++) {
                red[((rw * 2 + 0) * 32 + lane) * 4 + r] = c0[r];
                red[((rw * 2 + 1) * 32 + lane) * 4 + r] = c1[r];
            }
        }
        __syncthreads();
        if (kh == 0) {
            int rw = wid & 7;
            #pragma unroll
            for (int r = 0; r < 4; r++) {
                c0[r] += red[((rw * 2 + 0) * 32 + lane) * 4 + r];
                c1[r] += red[((rw * 2 + 1) * 32 + lane) * 4 + r];
            }
            int r0 = base + mt * 16 + (lane >> 2);
            int r1 = r0 + 8;
            int col0 = (ng * 2 + 0) * 8 + (lane & 3) * 2;
            int col1 = (ng * 2 + 1) * 8 + (lane & 3) * 2;
            if (r0 < N) {
                *(float2*)&out[(long long)r0 * COUT + col0] = make_float2(c0[0], c0[1]);
                *(float2*)&out[(long long)r0 * COUT + col1] = make_float2(c1[0], c1[1]);
            }
            if (r1 < N) {
                *(float2*)&out[(long long)r1 * COUT + col0] = make_float2(c0[2], c0[3]);
                *(float2*)&out[(long long)r1 * COUT + col1] = make_float2(c1[2], c1[3]);
            }
        }
    }
}

extern "C" void kernel_launch(void* const* d_in, const int* in_sizes, int n_in,
                              void* d_out, int out_size) {
    const float* q_pts     = (const float*)d_in[0];
    const float* neighbors = (const float*)d_in[2];
    const float* x         = (const float*)d_in[4];
    const float* kp        = (const float*)d_in[5];
    const float* W         = (const float*)d_in[6];
    float* out = (float*)d_out;

    int N = in_sizes[0] / 3;

    cudaFuncSetAttribute(kpconv_kernel,
                         cudaFuncAttributeMaxDynamicSharedMemorySize, SMEM_TOTAL);

    pack_bfrag<<<(8 * NKS * 32 + 255) / 256, 256>>>(W);
    int grid = (N + PBLK - 1) / PBLK;
    kpconv_kernel<<<grid, THREADS, SMEM_TOTAL>>>(q_pts, neighbors, x, kp, out, N);
}

// round 7
// speedup vs baseline: 2.4727x; 1.1851x over previous
#include <cuda_runtime.h>
#include <cuda_fp16.h>
#include <cstdint>

// KPConv fully tensorized: phase2 AND phase3 via HMMA m16n8k16.
// inputs: q_pts[N,3], s_pts(unused), neighbors[N,32,3], neighb_inds(unused),
//         x[N,32,64], kernel_points[15,3], weights[15,64,64] -> out[N,64] f32
//
// Per block (512 thr, 32 points), per 8-pt sub-batch:
//   phase1: w fp16 tile [16(kpt,pad)][32 m], row stride 80B (bank-conflict-free ldmatrix)
//   stage:  x fp16 tile [32 m][64 c] swizzled per point
//   phase2 MMA: wt[16][64] = w @ x, D frags stored into WT tile (phase-3 A layout)
// phase3: out[32][64] = wt[32][960] @ W via HMMA, B frags pre-packed in gmem.

#define KPTS 15
#define NNB  32
#define CIN  64
#define COUT 64
#define PBLK 32
#define SB   8
#define NSB  4
#define THREADS 512
#define NKS  60                  // 960 / 16
#define ROWB 1920                // wt row stride bytes
#define WT_BYTES (PBLK * ROWB)   // 61440
#define XSH_OFF  WT_BYTES        // x fp16 tiles: 8 * 4096 = 32768
#define W16_OFF  (XSH_OFF + SB * 4096)      // 94208; w16: 8 * 1280 = 10240
#define SMEM_TOTAL (W16_OFF + SB * 1280 + 1024)

typedef unsigned long long ull;

// B fragments for phase 3: [nt(8)][ks(60)][lane(32)] -> uint2 {b0, b1}
__device__ uint2 g_Bfrag[8 * NKS * 32];

static __device__ __forceinline__ uint32_t smem_u32(const void* p) {
    uint32_t a;
    asm("{ .reg .u64 t; cvta.to.shared.u64 t, %1; cvt.u32.u64 %0, t; }" : "=r"(a) : "l"(p));
    return a;
}
static __device__ __forceinline__ void ldm_x4(uint32_t& a0, uint32_t& a1,
                                              uint32_t& a2, uint32_t& a3, uint32_t addr) {
    asm volatile("ldmatrix.sync.aligned.m8n8.x4.shared.b16 {%0,%1,%2,%3}, [%4];"
                 : "=r"(a0), "=r"(a1), "=r"(a2), "=r"(a3) : "r"(addr));
}
static __device__ __forceinline__ void ldm_x4t(uint32_t& a0, uint32_t& a1,
                                               uint32_t& a2, uint32_t& a3, uint32_t addr) {
    asm volatile("ldmatrix.sync.aligned.m8n8.x4.trans.shared.b16 {%0,%1,%2,%3}, [%4];"
                 : "=r"(a0), "=r"(a1), "=r"(a2), "=r"(a3) : "r"(addr));
}
static __device__ __forceinline__ void mma16816(float* c, uint32_t a0, uint32_t a1,
                                                uint32_t a2, uint32_t a3,
                                                uint32_t b0, uint32_t b1) {
    asm volatile("mma.sync.aligned.m16n8k16.row.col.f32.f16.f16.f32 "
                 "{%0,%1,%2,%3}, {%4,%5,%6,%7}, {%8,%9}, {%0,%1,%2,%3};"
                 : "+f"(c[0]), "+f"(c[1]), "+f"(c[2]), "+f"(c[3])
                 : "r"(a0), "r"(a1), "r"(a2), "r"(a3), "r"(b0), "r"(b1));
}

__global__ void pack_bfrag(const float* __restrict__ W) {
    int i = blockIdx.x * blockDim.x + threadIdx.x;
    if (i >= 8 * NKS * 32) return;
    int lane = i & 31;
    int ks   = (i >> 5) % NKS;
    int nt   = i / (NKS * 32);
    int n  = nt * 8 + (lane >> 2);
    int j0 = ks * 16 + (lane & 3) * 2;
    __half2 b0 = __floats2half2_rn(W[(j0 + 0) * COUT + n], W[(j0 + 1) * COUT + n]);
    __half2 b1 = __floats2half2_rn(W[(j0 + 8) * COUT + n], W[(j0 + 9) * COUT + n]);
    uint2 v;
    v.x = *(const uint32_t*)&b0;
    v.y = *(const uint32_t*)&b1;
    g_Bfrag[i] = v;
}

__global__ __launch_bounds__(THREADS, 2)
void kpconv_kernel(const float* __restrict__ q_pts,
                   const float* __restrict__ neighbors,
                   const float* __restrict__ x,
                   const float* __restrict__ kernel_points,
                   float* __restrict__ out,
                   int N)
{
    extern __shared__ char smem_raw[];
    char* smem = (char*)(((uintptr_t)smem_raw + 1023) & ~(uintptr_t)1023);
    char* wt_sh = smem;                      // fp16 A tile for phase 3 (32 rows)
    char* x_sh  = smem + XSH_OFF;            // fp16 x tiles, 8 pts
    char* w16   = smem + W16_OFF;            // fp16 w tiles, 8 pts, 80B row stride
    __shared__ float kp_sh[KPTS * 3];
    const uint32_t sb_u32  = smem_u32(smem);
    const uint32_t wt_u32  = sb_u32;
    const uint32_t xsh_u32 = sb_u32 + XSH_OFF;
    const uint32_t w16_u32 = sb_u32 + W16_OFF;

    const int tid  = threadIdx.x;
    const int wid  = tid >> 5;
    const int lane = tid & 31;
    const int base = blockIdx.x * PBLK;

    if (tid < KPTS * 3) kp_sh[tid] = kernel_points[tid];
    __syncthreads();

    const float inv_ext = 1.0f / 0.06f;

    #pragma unroll 1
    for (int sb = 0; sb < NSB; sb++) {
        // ---- Phase 1: w fp16 tiles for 8 points (threads 0..255) ----
        if (tid < SB * NNB) {
            int p = tid >> 5, m = tid & 31;
            int np = base + sb * SB + p; if (np >= N) np = N - 1;
            float qx = q_pts[np * 3 + 0];
            float qy = q_pts[np * 3 + 1];
            float qz = q_pts[np * 3 + 2];
            int nb = (np * NNB + m) * 3;
            float rx = neighbors[nb + 0] - qx;
            float ry = neighbors[nb + 1] - qy;
            float rz = neighbors[nb + 2] - qz;
            char* wrow = w16 + p * 1280 + m * 2;
            #pragma unroll
            for (int k = 0; k < KPTS; k++) {
                float dx = rx - kp_sh[k * 3 + 0];
                float dy = ry - kp_sh[k * 3 + 1];
                float dz = rz - kp_sh[k * 3 + 2];
                float sq = dx * dx + dy * dy + dz * dz;
                float w = fmaxf(1.0f - sqrtf(sq) * inv_ext, 0.0f);
                *(__half*)(wrow + k * 80) = __float2half_rn(w);
            }
            *(__half*)(wrow + 15 * 80) = __float2half_rn(0.0f);  // pad row
        }

        // ---- Stage x fp16: warp -> (point p = wid>>1, rows mb..mb+15) ----
        {
            int p  = wid >> 1;
            int mb = (wid & 1) * 16;
            int np = base + sb * SB + p; if (np >= N) np = N - 1;
            const float4* xr = (const float4*)(x + (long long)np * NNB * CIN);
            char* xt = x_sh + p * 4096;
            #pragma unroll
            for (int r = 0; r < 8; r++) {
                int m  = mb + 2 * r + (lane >> 4);
                int c4 = (lane & 15) * 4;
                float4 v = __ldg(xr + m * 16 + (lane & 15));
                __half2 h0 = __floats2half2_rn(v.x, v.y);
                __half2 h1 = __floats2half2_rn(v.z, v.w);
                uint2 st;
                st.x = *(const uint32_t*)&h0;
                st.y = *(const uint32_t*)&h1;
                int chunk = (c4 >> 3) ^ (m & 7);
                *(uint2*)(xt + m * 128 + chunk * 16 + (c4 & 7) * 2) = st;
            }
        }
        __syncthreads();

        // ---- Phase 2 MMA: wt[16][64] = w[16][32] @ x[32][64] ----
        {
            int p  = wid >> 1;
            int ch = wid & 1;                    // c-half: c in [32*ch, 32*ch+32)
            uint32_t wp = w16_u32 + p * 1280;
            uint32_t xp = xsh_u32 + p * 4096;
            int g = lane >> 3;

            float d[4][4];
            #pragma unroll
            for (int i = 0; i < 4; i++)
                #pragma unroll
                for (int j = 0; j < 4; j++) d[i][j] = 0.f;

            #pragma unroll
            for (int s = 0; s < 2; s++) {
                uint32_t a0, a1, a2, a3;
                ldm_x4(a0, a1, a2, a3,
                       wp + ((g & 1) * 8 + (lane & 7)) * 80 + s * 32 + (g >> 1) * 16);
                int row = s * 16 + (g & 1) * 8 + (lane & 7);
                #pragma unroll
                for (int ntp = 0; ntp < 2; ntp++) {
                    int nt = ch * 4 + ntp * 2 + (g >> 1);
                    uint32_t b0, b1, b2, b3;
                    ldm_x4t(b0, b1, b2, b3,
                            xp + row * 128 + ((nt ^ (row & 7)) << 4));
                    mma16816(d[ntp * 2 + 0], a0, a1, a2, a3, b0, b1);
                    mma16816(d[ntp * 2 + 1], a0, a1, a2, a3, b2, b3);
                }
            }

            // store D -> WT tile (phase-3 A layout)
            int lr = sb * SB + p;
            char* row = wt_sh + lr * ROWB;
            int sw = lr & 7;
            #pragma unroll
            for (int nt4 = 0; nt4 < 4; nt4++) {
                #pragma unroll
                for (int rh = 0; rh < 2; rh++) {
                    int kpt = (lane >> 2) + rh * 8;
                    if (kpt < KPTS) {
                        int c = ch * 32 + nt4 * 8 + (lane & 3) * 2;
                        __half2 h = __floats2half2_rn(d[nt4][rh * 2], d[nt4][rh * 2 + 1]);
                        int chunk = (kpt * 8 + (c >> 3)) ^ sw;
                        *(__half2*)(row + chunk * 16 + (c & 7) * 2) = h;
                    }
                }
            }
        }
        __syncthreads();
    }

    // ---- Phase 3: HMMA GEMM out[32][64] = wt @ W ----
    {
        const int kh = wid >> 3;
        const int mt = (wid >> 2) & 1;
        const int ng = wid & 3;
        const int rowA = mt * 16 + (lane & 15);
        const uint32_t a_row = wt_u32 + rowA * ROWB;
        const int swA = rowA & 7;
        const int khalf = lane >> 4;

        float c0[4] = {0.f, 0.f, 0.f, 0.f};
        float c1[4] = {0.f, 0.f, 0.f, 0.f};
        const uint2* Bf0 = g_Bfrag + ((ng * 2 + 0) * NKS) * 32 + lane;
        const uint2* Bf1 = g_Bfrag + ((ng * 2 + 1) * NKS) * 32 + lane;

        #pragma unroll 5
        for (int s = 0; s < NKS / 2; s++) {
            int ks = kh * (NKS / 2) + s;
            uint32_t addr = a_row + ((((ks << 1) + khalf) ^ swA) << 4);
            uint32_t a0, a1, a2, a3;
            ldm_x4(a0, a1, a2, a3, addr);
            uint2 b0 = __ldg(Bf0 + ks * 32);
            uint2 b1 = __ldg(Bf1 + ks * 32);
            mma16816(c0, a0, a1, a2, a3, b0.x, b0.y);
            mma16816(c1, a0, a1, a2, a3, b1.x, b1.y);
        }

        // reduce across K-halves via smem (alias over x_sh)
        float* red = (float*)x_sh;          // 8192 B <= 32768
        __syncthreads();
        if (kh == 1) {
            int rw = wid & 7;
            #pragma unroll
            for (int r = 0; r < 4; r++) {
                red[((rw * 2 + 0) * 32 + lane) * 4 + r] = c0[r];
                red[((rw * 2 + 1) * 32 + lane) * 4 + r] = c1[r];
            }
        }
        __syncthreads();
        if (kh == 0) {
            int rw = wid & 7;
            #pragma unroll
            for (int r = 0; r < 4; r++) {
                c0[r] += red[((rw * 2 + 0) * 32 + lane) * 4 + r];
                c1[r] += red[((rw * 2 + 1) * 32 + lane) * 4 + r];
            }
            int r0 = base + mt * 16 + (lane >> 2);
            int r1 = r0 + 8;
            int col0 = (ng * 2 + 0) * 8 + (lane & 3) * 2;
            int col1 = (ng * 2 + 1) * 8 + (lane & 3) * 2;
            if (r0 < N) {
                *(float2*)&out[(long long)r0 * COUT + col0] = make_float2(c0[0], c0[1]);
                *(float2*)&out[(long long)r0 * COUT + col1] = make_float2(c1[0], c1[1]);
            }
            if (r1 < N) {
                *(float2*)&out[(long long)r1 * COUT + col0] = make_float2(c0[2], c0[3]);
                *(float2*)&out[(long long)r1 * COUT + col1] = make_float2(c1[2], c1[3]);
            }
        }
    }
}

extern "C" void kernel_launch(void* const* d_in, const int* in_sizes, int n_in,
                              void* d_out, int out_size) {
    const float* q_pts     = (const float*)d_in[0];
    const float* neighbors = (const float*)d_in[2];
    const float* x         = (const float*)d_in[4];
    const float* kp        = (const float*)d_in[5];
    const float* W         = (const float*)d_in[6];
    float* out = (float*)d_out;

    int N = in_sizes[0] / 3;

    cudaFuncSetAttribute(kpconv_kernel,
                         cudaFuncAttributeMaxDynamicSharedMemorySize, SMEM_TOTAL);

    pack_bfrag<<<(8 * NKS * 32 + 255) / 256, 256>>>(W);
    int grid = (N + PBLK - 1) / PBLK;
    kpconv_kernel<<<grid, THREADS, SMEM_TOTAL>>>(q_pts, neighbors, x, kp, out, N);
}

// round 8
// speedup vs baseline: 2.5309x; 1.0235x over previous
#include <cuda_runtime.h>
#include <cuda_fp16.h>
#include <cstdint>

// KPConv fully tensorized + software-pipelined quarter-batches.
// inputs: q_pts[N,3], s_pts(unused), neighbors[N,32,3], neighb_inds(unused),
//         x[N,32,64], kernel_points[15,3], weights[15,64,64] -> out[N,64] f32
//
// Per block (512 thr, 32 points), 8 quarter-batches (QB) of 4 points, pipelined:
//   top:    prefetch LDG x(q+1) + neighbors(q+1) into regs
//   mid:    phase2 MMA of q  (hides prefetch latency)
//   bottom: phase1 w(q+1) from regs -> w16 buf; cvt+STS x(q+1) -> x_sh buf
// phase3: out[32][64] = wt[32][960] @ W via HMMA, B frags pre-packed in gmem.

#define KPTS 15
#define NNB  32
#define CIN  64
#define COUT 64
#define PBLK 32
#define QB   4
#define NQB  8
#define THREADS 512
#define NKS  60                  // 960 / 16
#define ROWB 1920                // wt row stride bytes
#define WT_BYTES (PBLK * ROWB)   // 61440
#define XSH_OFF  WT_BYTES        // x fp16 tiles: 2 bufs * 4 pts * 4096 = 32768
#define XBUF     16384
#define W16_OFF  (XSH_OFF + 2 * XBUF)        // 94208
#define WBUF     5120                        // 4 pts * 1280
#define SMEM_TOTAL (W16_OFF + 2 * WBUF + 1024)

typedef unsigned long long ull;

// B fragments for phase 3: [nt(8)][ks(60)][lane(32)] -> uint2 {b0, b1}
__device__ uint2 g_Bfrag[8 * NKS * 32];

static __device__ __forceinline__ uint32_t smem_u32(const void* p) {
    uint32_t a;
    asm("{ .reg .u64 t; cvta.to.shared.u64 t, %1; cvt.u32.u64 %0, t; }" : "=r"(a) : "l"(p));
    return a;
}
static __device__ __forceinline__ void ldm_x4(uint32_t& a0, uint32_t& a1,
                                              uint32_t& a2, uint32_t& a3, uint32_t addr) {
    asm volatile("ldmatrix.sync.aligned.m8n8.x4.shared.b16 {%0,%1,%2,%3}, [%4];"
                 : "=r"(a0), "=r"(a1), "=r"(a2), "=r"(a3) : "r"(addr));
}
static __device__ __forceinline__ void ldm_x4t(uint32_t& a0, uint32_t& a1,
                                               uint32_t& a2, uint32_t& a3, uint32_t addr) {
    asm volatile("ldmatrix.sync.aligned.m8n8.x4.trans.shared.b16 {%0,%1,%2,%3}, [%4];"
                 : "=r"(a0), "=r"(a1), "=r"(a2), "=r"(a3) : "r"(addr));
}
static __device__ __forceinline__ void mma16816(float* c, uint32_t a0, uint32_t a1,
                                                uint32_t a2, uint32_t a3,
                                                uint32_t b0, uint32_t b1) {
    asm volatile("mma.sync.aligned.m16n8k16.row.col.f32.f16.f16.f32 "
                 "{%0,%1,%2,%3}, {%4,%5,%6,%7}, {%8,%9}, {%0,%1,%2,%3};"
                 : "+f"(c[0]), "+f"(c[1]), "+f"(c[2]), "+f"(c[3])
                 : "r"(a0), "r"(a1), "r"(a2), "r"(a3), "r"(b0), "r"(b1));
}

__global__ void pack_bfrag(const float* __restrict__ W) {
    int i = blockIdx.x * blockDim.x + threadIdx.x;
    if (i >= 8 * NKS * 32) return;
    int lane = i & 31;
    int ks   = (i >> 5) % NKS;
    int nt   = i / (NKS * 32);
    int n  = nt * 8 + (lane >> 2);
    int j0 = ks * 16 + (lane & 3) * 2;
    __half2 b0 = __floats2half2_rn(W[(j0 + 0) * COUT + n], W[(j0 + 1) * COUT + n]);
    __half2 b1 = __floats2half2_rn(W[(j0 + 8) * COUT + n], W[(j0 + 9) * COUT + n]);
    uint2 v;
    v.x = *(const uint32_t*)&b0;
    v.y = *(const uint32_t*)&b1;
    g_Bfrag[i] = v;
}

__global__ __launch_bounds__(THREADS, 2)
void kpconv_kernel(const float* __restrict__ q_pts,
                   const float* __restrict__ neighbors,
                   const float* __restrict__ x,
                   const float* __restrict__ kernel_points,
                   float* __restrict__ out,
                   int N)
{
    extern __shared__ char smem_raw[];
    char* smem = (char*)(((uintptr_t)smem_raw + 1023) & ~(uintptr_t)1023);
    char* wt_sh = smem;                      // fp16 A tile for phase 3 (32 rows)
    char* x_sh  = smem + XSH_OFF;            // fp16 x tiles, 2 bufs x 4 pts
    char* w16   = smem + W16_OFF;            // fp16 w tiles, 2 bufs x 4 pts
    __shared__ float kp_sh[KPTS * 3];
    const uint32_t sb_u32  = smem_u32(smem);
    const uint32_t wt_u32  = sb_u32;
    const uint32_t xsh_u32 = sb_u32 + XSH_OFF;
    const uint32_t w16_u32 = sb_u32 + W16_OFF;

    const int tid  = threadIdx.x;
    const int wid  = tid >> 5;
    const int lane = tid & 31;
    const int base = blockIdx.x * PBLK;

    if (tid < KPTS * 3) kp_sh[tid] = kernel_points[tid];
    __syncthreads();

    const float inv_ext = 1.0f / 0.06f;

    // staging geometry: warp -> point (wid>>2), row group (wid&3)
    const int sp  = wid >> 2;
    const int rg  = wid & 3;
    // phase1 geometry: item i = tid>>2 (p1, m1), k-quarter kq = tid&3
    const int i1  = tid >> 2;
    const int p1  = i1 >> 5;
    const int m1  = i1 & 31;
    const int kq  = tid & 3;

    float4 xf[4];
    float rx, ry, rz;

    // ---------- helpers as macros over locals ----------
#define LDG_X(qb)                                                            \
    {                                                                        \
        int np = base + (qb) * QB + sp; if (np >= N) np = N - 1;             \
        const float4* xr = (const float4*)(x + (long long)np * NNB * CIN);   \
        _Pragma("unroll")                                                    \
        for (int it = 0; it < 4; it++) {                                     \
            int m = rg * 8 + it * 2 + (lane >> 4);                           \
            xf[it] = __ldg(xr + m * 16 + (lane & 15));                       \
        }                                                                    \
    }

#define LDG_NBR(qb)                                                          \
    {                                                                        \
        int np = base + (qb) * QB + p1; if (np >= N) np = N - 1;             \
        float qx = q_pts[np * 3 + 0];                                        \
        float qy = q_pts[np * 3 + 1];                                        \
        float qz = q_pts[np * 3 + 2];                                        \
        int nb = (np * NNB + m1) * 3;                                        \
        rx = neighbors[nb + 0] - qx;                                         \
        ry = neighbors[nb + 1] - qy;                                         \
        rz = neighbors[nb + 2] - qz;                                         \
    }

#define PHASE1_ST(buf)                                                       \
    {                                                                        \
        char* wrow = w16 + (buf) * WBUF + p1 * 1280 + m1 * 2;                \
        _Pragma("unroll")                                                    \
        for (int kk = 0; kk < 4; kk++) {                                     \
            int k = kq * 4 + kk;                                             \
            float w = 0.0f;                                                  \
            if (k < KPTS) {                                                  \
                float dx = rx - kp_sh[k * 3 + 0];                            \
                float dy = ry - kp_sh[k * 3 + 1];                            \
                float dz = rz - kp_sh[k * 3 + 2];                            \
                float sq = dx * dx + dy * dy + dz * dz;                      \
                w = fmaxf(1.0f - sqrtf(sq) * inv_ext, 0.0f);                 \
            }                                                                \
            *(__half*)(wrow + k * 80) = __float2half_rn(w);                  \
        }                                                                    \
    }

#define STS_X(buf)                                                           \
    {                                                                        \
        char* xt = x_sh + (buf) * XBUF + sp * 4096;                          \
        _Pragma("unroll")                                                    \
        for (int it = 0; it < 4; it++) {                                     \
            int m  = rg * 8 + it * 2 + (lane >> 4);                          \
            int c4 = (lane & 15) * 4;                                        \
            __half2 h0 = __floats2half2_rn(xf[it].x, xf[it].y);              \
            __half2 h1 = __floats2half2_rn(xf[it].z, xf[it].w);              \
            uint2 st;                                                        \
            st.x = *(const uint32_t*)&h0;                                    \
            st.y = *(const uint32_t*)&h1;                                    \
            int chunk = (c4 >> 3) ^ (m & 7);                                 \
            *(uint2*)(xt + m * 128 + chunk * 16 + (c4 & 7) * 2) = st;        \
        }                                                                    \
    }

    // ---------- prologue: fill buffers for qb = 0 ----------
    LDG_X(0)
    LDG_NBR(0)
    PHASE1_ST(0)
    STS_X(0)
    __syncthreads();

    // ---------- pipelined main loop ----------
    #pragma unroll 1
    for (int q = 0; q < NQB; q++) {
        if (q < NQB - 1) {
            LDG_X(q + 1)
            LDG_NBR(q + 1)
        }

        // ---- phase2 MMA for qb=q: wt[16][64] = w[16][32] @ x[32][64] ----
        {
            const int buf = q & 1;
            const int p  = wid >> 2;
            const int qn = wid & 3;              // nt pair
            uint32_t wp = w16_u32 + buf * WBUF + p * 1280;
            uint32_t xp = xsh_u32 + buf * XBUF + p * 4096;
            int g = lane >> 3;

            float d0[4] = {0.f, 0.f, 0.f, 0.f};
            float d1[4] = {0.f, 0.f, 0.f, 0.f};
            #pragma unroll
            for (int s = 0; s < 2; s++) {
                uint32_t a0, a1, a2, a3;
                ldm_x4(a0, a1, a2, a3,
                       wp + ((g & 1) * 8 + (lane & 7)) * 80 + s * 32 + (g >> 1) * 16);
                int row = s * 16 + (g & 1) * 8 + (lane & 7);
                int nt  = qn * 2 + (g >> 1);
                uint32_t b0, b1, b2, b3;
                ldm_x4t(b0, b1, b2, b3,
                        xp + row * 128 + ((nt ^ (row & 7)) << 4));
                mma16816(d0, a0, a1, a2, a3, b0, b1);
                mma16816(d1, a0, a1, a2, a3, b2, b3);
            }

            // store D -> WT tile (phase-3 A layout)
            int lr = q * QB + p;
            char* row_ = wt_sh + lr * ROWB;
            int sw = lr & 7;
            #pragma unroll
            for (int i = 0; i < 2; i++) {
                const float* dd = i ? d1 : d0;
                #pragma unroll
                for (int rh = 0; rh < 2; rh++) {
                    int kpt = (lane >> 2) + rh * 8;
                    if (kpt < KPTS) {
                        int c = (qn * 2 + i) * 8 + (lane & 3) * 2;
                        __half2 h = __floats2half2_rn(dd[rh * 2], dd[rh * 2 + 1]);
                        int chunk = (kpt * 8 + (c >> 3)) ^ sw;
                        *(__half2*)(row_ + chunk * 16 + (c & 7) * 2) = h;
                    }
                }
            }
        }

        if (q < NQB - 1) {
            PHASE1_ST((q + 1) & 1)
            STS_X((q + 1) & 1)
        }
        __syncthreads();
    }

    // ---------- Phase 3: HMMA GEMM out[32][64] = wt @ W ----------
    {
        const int kh = wid >> 3;
        const int mt = (wid >> 2) & 1;
        const int ng = wid & 3;
        const int rowA = mt * 16 + (lane & 15);
        const uint32_t a_row = wt_u32 + rowA * ROWB;
        const int swA = rowA & 7;
        const int khalf = lane >> 4;

        float c0[4] = {0.f, 0.f, 0.f, 0.f};
        float c1[4] = {0.f, 0.f, 0.f, 0.f};
        const uint2* Bf0 = g_Bfrag + ((ng * 2 + 0) * NKS) * 32 + lane;
        const uint2* Bf1 = g_Bfrag + ((ng * 2 + 1) * NKS) * 32 + lane;

        #pragma unroll 5
        for (int s = 0; s < NKS / 2; s++) {
            int ks = kh * (NKS / 2) + s;
            uint32_t addr = a_row + ((((ks << 1) + khalf) ^ swA) << 4);
            uint32_t a0, a1, a2, a3;
            ldm_x4(a0, a1, a2, a3, addr);
            uint2 b0 = __ldg(Bf0 + ks * 32);
            uint2 b1 = __ldg(Bf1 + ks * 32);
            mma16816(c0, a0, a1, a2, a3, b0.x, b0.y);
            mma16816(c1, a0, a1, a2, a3, b1.x, b1.y);
        }

        // reduce across K-halves via smem (alias over x_sh)
        float* red = (float*)x_sh;          // 8192 B <= 32768
        __syncthreads();
        if (kh == 1) {
            int rw = wid & 7;
            #pragma unroll
            for (int r = 0; r < 4; r++) {
                red[((rw * 2 + 0) * 32 + lane) * 4 + r] = c0[r];
                red[((rw * 2 + 1) * 32 + lane) * 4 + r] = c1[r];
            }
        }
        __syncthreads();
        if (kh == 0) {
            int rw = wid & 7;
            #pragma unroll
            for (int r = 0; r < 4; r++) {
                c0[r] += red[((rw * 2 + 0) * 32 + lane) * 4 + r];
                c1[r] += red[((rw * 2 + 1) * 32 + lane) * 4 + r];
            }
            int r0 = base + mt * 16 + (lane >> 2);
            int r1 = r0 + 8;
            int col0 = (ng * 2 + 0) * 8 + (lane & 3) * 2;
            int col1 = (ng * 2 + 1) * 8 + (lane & 3) * 2;
            if (r0 < N) {
                *(float2*)&out[(long long)r0 * COUT + col0] = make_float2(c0[0], c0[1]);
                *(float2*)&out[(long long)r0 * COUT + col1] = make_float2(c1[0], c1[1]);
            }
            if (r1 < N) {
                *(float2*)&out[(long long)r1 * COUT + col0] = make_float2(c0[2], c0[3]);
                *(float2*)&out[(long long)r1 * COUT + col1] = make_float2(c1[2], c1[3]);
            }
        }
    }
}

extern "C" void kernel_launch(void* const* d_in, const int* in_sizes, int n_in,
                              void* d_out, int out_size) {
    const float* q_pts     = (const float*)d_in[0];
    const float* neighbors = (const float*)d_in[2];
    const float* x         = (const float*)d_in[4];
    const float* kp        = (const float*)d_in[5];
    const float* W         = (const float*)d_in[6];
    float* out = (float*)d_out;

    int N = in_sizes[0] / 3;

    cudaFuncSetAttribute(kpconv_kernel,
                         cudaFuncAttributeMaxDynamicSharedMemorySize, SMEM_TOTAL);

    pack_bfrag<<<(8 * NKS * 32 + 255) / 256, 256>>>(W);
    int grid = (N + PBLK - 1) / PBLK;
    kpconv_kernel<<<grid, THREADS, SMEM_TOTAL>>>(q_pts, neighbors, x, kp, out, N);
}

// round 9
// speedup vs baseline: 2.8413x; 1.1226x over previous
#include <cuda_runtime.h>
#include <cuda_fp16.h>
#include <cstdint>

// KPConv fully tensorized, pipelined, small-CTA (256 thr / 16 pts / 4 CTAs per SM).
// inputs: q_pts[N,3], s_pts(unused), neighbors[N,32,3], neighb_inds(unused),
//         x[N,32,64], kernel_points[15,3], weights[15,64,64] -> out[N,64] f32

#define KPTS 15
#define NNB  32
#define CIN  64
#define COUT 64
#define PBLK 16
#define QB   2
#define NQB  8
#define THREADS 256
#define NKS  60                  // 960 / 16
#define ROWB 1920                // wt row stride bytes
#define WT_BYTES (PBLK * ROWB)   // 30720
#define XSH_OFF  WT_BYTES
#define XBUF     8192            // 2 pts * 4096
#define W16_OFF  (XSH_OFF + 2 * XBUF)        // 47104
#define WBUF     2560                        // 2 pts * 1280
#define SMEM_TOTAL (W16_OFF + 2 * WBUF + 1024)

typedef unsigned long long ull;

// B fragments for phase 3: [nt(8)][ks(60)][lane(32)] -> uint2 {b0, b1}
__device__ uint2 g_Bfrag[8 * NKS * 32];

static __device__ __forceinline__ uint32_t smem_u32(const void* p) {
    uint32_t a;
    asm("{ .reg .u64 t; cvta.to.shared.u64 t, %1; cvt.u32.u64 %0, t; }" : "=r"(a) : "l"(p));
    return a;
}
static __device__ __forceinline__ void ldm_x4(uint32_t& a0, uint32_t& a1,
                                              uint32_t& a2, uint32_t& a3, uint32_t addr) {
    asm volatile("ldmatrix.sync.aligned.m8n8.x4.shared.b16 {%0,%1,%2,%3}, [%4];"
                 : "=r"(a0), "=r"(a1), "=r"(a2), "=r"(a3) : "r"(addr));
}
static __device__ __forceinline__ void ldm_x4t(uint32_t& a0, uint32_t& a1,
                                               uint32_t& a2, uint32_t& a3, uint32_t addr) {
    asm volatile("ldmatrix.sync.aligned.m8n8.x4.trans.shared.b16 {%0,%1,%2,%3}, [%4];"
                 : "=r"(a0), "=r"(a1), "=r"(a2), "=r"(a3) : "r"(addr));
}
static __device__ __forceinline__ void mma16816(float* c, uint32_t a0, uint32_t a1,
                                                uint32_t a2, uint32_t a3,
                                                uint32_t b0, uint32_t b1) {
    asm volatile("mma.sync.aligned.m16n8k16.row.col.f32.f16.f16.f32 "
                 "{%0,%1,%2,%3}, {%4,%5,%6,%7}, {%8,%9}, {%0,%1,%2,%3};"
                 : "+f"(c[0]), "+f"(c[1]), "+f"(c[2]), "+f"(c[3])
                 : "r"(a0), "r"(a1), "r"(a2), "r"(a3), "r"(b0), "r"(b1));
}

__global__ void pack_bfrag(const float* __restrict__ W) {
    int i = blockIdx.x * blockDim.x + threadIdx.x;
    if (i >= 8 * NKS * 32) return;
    int lane = i & 31;
    int ks   = (i >> 5) % NKS;
    int nt   = i / (NKS * 32);
    int n  = nt * 8 + (lane >> 2);
    int j0 = ks * 16 + (lane & 3) * 2;
    __half2 b0 = __floats2half2_rn(W[(j0 + 0) * COUT + n], W[(j0 + 1) * COUT + n]);
    __half2 b1 = __floats2half2_rn(W[(j0 + 8) * COUT + n], W[(j0 + 9) * COUT + n]);
    uint2 v;
    v.x = *(const uint32_t*)&b0;
    v.y = *(const uint32_t*)&b1;
    g_Bfrag[i] = v;
}

__global__ __launch_bounds__(THREADS, 4)
void kpconv_kernel(const float* __restrict__ q_pts,
                   const float* __restrict__ neighbors,
                   const float* __restrict__ x,
                   const float* __restrict__ kernel_points,
                   float* __restrict__ out,
                   int N)
{
    extern __shared__ char smem_raw[];
    char* smem = (char*)(((uintptr_t)smem_raw + 1023) & ~(uintptr_t)1023);
    char* wt_sh = smem;                      // fp16 A tile for phase 3 (16 rows)
    char* x_sh  = smem + XSH_OFF;            // fp16 x tiles, 2 bufs x 2 pts
    char* w16   = smem + W16_OFF;            // fp16 w tiles, 2 bufs x 2 pts
    __shared__ float kp_sh[KPTS * 3];
    const uint32_t sb_u32  = smem_u32(smem);
    const uint32_t wt_u32  = sb_u32;
    const uint32_t xsh_u32 = sb_u32 + XSH_OFF;
    const uint32_t w16_u32 = sb_u32 + W16_OFF;

    const int tid  = threadIdx.x;
    const int wid  = tid >> 5;
    const int lane = tid & 31;
    const int base = blockIdx.x * PBLK;

    if (tid < KPTS * 3) kp_sh[tid] = kernel_points[tid];
    __syncthreads();

    const float inv_ext = 1.0f / 0.06f;

    // staging geometry: warp -> point (wid>>2), row group (wid&3)
    const int sp  = wid >> 2;
    const int rg  = wid & 3;
    // phase1 geometry: item i = tid>>2 (p1, m1), k-quarter kq = tid&3
    const int i1  = tid >> 2;
    const int p1  = i1 >> 5;
    const int m1  = i1 & 31;
    const int kq  = tid & 3;

    float4 xf[4];
    float rx, ry, rz;

#define LDG_X(qb)                                                            \
    {                                                                        \
        int np = base + (qb) * QB + sp; if (np >= N) np = N - 1;             \
        const float4* xr = (const float4*)(x + (long long)np * NNB * CIN);   \
        _Pragma("unroll")                                                    \
        for (int it = 0; it < 4; it++) {                                     \
            int m = rg * 8 + it * 2 + (lane >> 4);                           \
            xf[it] = __ldg(xr + m * 16 + (lane & 15));                       \
        }                                                                    \
    }

#define LDG_NBR(qb)                                                          \
    {                                                                        \
        int np = base + (qb) * QB + p1; if (np >= N) np = N - 1;             \
        float qx = q_pts[np * 3 + 0];                                        \
        float qy = q_pts[np * 3 + 1];                                        \
        float qz = q_pts[np * 3 + 2];                                        \
        int nb = (np * NNB + m1) * 3;                                        \
        rx = neighbors[nb + 0] - qx;                                         \
        ry = neighbors[nb + 1] - qy;                                         \
        rz = neighbors[nb + 2] - qz;                                         \
    }

#define PHASE1_ST(buf)                                                       \
    {                                                                        \
        char* wrow = w16 + (buf) * WBUF + p1 * 1280 + m1 * 2;                \
        _Pragma("unroll")                                                    \
        for (int kk = 0; kk < 4; kk++) {                                     \
            int k = kq * 4 + kk;                                             \
            float w = 0.0f;                                                  \
            if (k < KPTS) {                                                  \
                float dx = rx - kp_sh[k * 3 + 0];                            \
                float dy = ry - kp_sh[k * 3 + 1];                            \
                float dz = rz - kp_sh[k * 3 + 2];                            \
                float sq = dx * dx + dy * dy + dz * dz;                      \
                w = fmaxf(1.0f - sqrtf(sq) * inv_ext, 0.0f);                 \
            }                                                                \
            *(__half*)(wrow + k * 80) = __float2half_rn(w);                  \
        }                                                                    \
    }

#define STS_X(buf)                                                           \
    {                                                                        \
        char* xt = x_sh + (buf) * XBUF + sp * 4096;                          \
        _Pragma("unroll")                                                    \
        for (int it = 0; it < 4; it++) {                                     \
            int m  = rg * 8 + it * 2 + (lane >> 4);                          \
            int c4 = (lane & 15) * 4;                                        \
            __half2 h0 = __floats2half2_rn(xf[it].x, xf[it].y);              \
            __half2 h1 = __floats2half2_rn(xf[it].z, xf[it].w);              \
            uint2 st;                                                        \
            st.x = *(const uint32_t*)&h0;                                    \
            st.y = *(const uint32_t*)&h1;                                    \
            int chunk = (c4 >> 3) ^ (m & 7);                                 \
            *(uint2*)(xt + m * 128 + chunk * 16 + (c4 & 7) * 2) = st;        \
        }                                                                    \
    }

    // ---------- prologue ----------
    LDG_X(0)
    LDG_NBR(0)
    PHASE1_ST(0)
    STS_X(0)
    __syncthreads();

    // ---------- pipelined main loop ----------
    #pragma unroll 1
    for (int q = 0; q < NQB; q++) {
        if (q < NQB - 1) {
            LDG_X(q + 1)
            LDG_NBR(q + 1)
        }

        // ---- phase2 MMA for qb=q: wt[16][64] = w[16][32] @ x[32][64] ----
        {
            const int buf = q & 1;
            const int p  = wid >> 2;             // 0..1
            const int qn = wid & 3;              // nt pair
            uint32_t wp = w16_u32 + buf * WBUF + p * 1280;
            uint32_t xp = xsh_u32 + buf * XBUF + p * 4096;
            int g = lane >> 3;

            float d0[4] = {0.f, 0.f, 0.f, 0.f};
            float d1[4] = {0.f, 0.f, 0.f, 0.f};
            #pragma unroll
            for (int s = 0; s < 2; s++) {
                uint32_t a0, a1, a2, a3;
                ldm_x4(a0, a1, a2, a3,
                       wp + ((g & 1) * 8 + (lane & 7)) * 80 + s * 32 + (g >> 1) * 16);
                int row = s * 16 + (g & 1) * 8 + (lane & 7);
                int nt  = qn * 2 + (g >> 1);
                uint32_t b0, b1, b2, b3;
                ldm_x4t(b0, b1, b2, b3,
                        xp + row * 128 + ((nt ^ (row & 7)) << 4));
                mma16816(d0, a0, a1, a2, a3, b0, b1);
                mma16816(d1, a0, a1, a2, a3, b2, b3);
            }

            // store D -> WT tile (phase-3 A layout)
            int lr = q * QB + p;
            char* row_ = wt_sh + lr * ROWB;
            int sw = lr & 7;
            #pragma unroll
            for (int i = 0; i < 2; i++) {
                const float* dd = i ? d1 : d0;
                #pragma unroll
                for (int rh = 0; rh < 2; rh++) {
                    int kpt = (lane >> 2) + rh * 8;
                    if (kpt < KPTS) {
                        int c = (qn * 2 + i) * 8 + (lane & 3) * 2;
                        __half2 h = __floats2half2_rn(dd[rh * 2], dd[rh * 2 + 1]);
                        int chunk = (kpt * 8 + (c >> 3)) ^ sw;
                        *(__half2*)(row_ + chunk * 16 + (c & 7) * 2) = h;
                    }
                }
            }
        }

        if (q < NQB - 1) {
            PHASE1_ST((q + 1) & 1)
            STS_X((q + 1) & 1)
        }
        __syncthreads();
    }

    // ---------- Phase 3: HMMA GEMM out[16][64] = wt @ W ----------
    {
        const int kh = wid >> 2;                 // K-half
        const int ng = wid & 3;                  // n-group (2 n-tiles)
        const int rowA = lane & 15;
        const uint32_t a_row = wt_u32 + rowA * ROWB;
        const int swA = rowA & 7;
        const int khalf = lane >> 4;

        float c0[4] = {0.f, 0.f, 0.f, 0.f};
        float c1[4] = {0.f, 0.f, 0.f, 0.f};
        const uint2* Bf0 = g_Bfrag + ((ng * 2 + 0) * NKS) * 32 + lane;
        const uint2* Bf1 = g_Bfrag + ((ng * 2 + 1) * NKS) * 32 + lane;

        #pragma unroll 5
        for (int s = 0; s < NKS / 2; s++) {
            int ks = kh * (NKS / 2) + s;
            uint32_t addr = a_row + ((((ks << 1) + khalf) ^ swA) << 4);
            uint32_t a0, a1, a2, a3;
            ldm_x4(a0, a1, a2, a3, addr);
            uint2 b0 = __ldg(Bf0 + ks * 32);
            uint2 b1 = __ldg(Bf1 + ks * 32);
            mma16816(c0, a0, a1, a2, a3, b0.x, b0.y);
            mma16816(c1, a0, a1, a2, a3, b1.x, b1.y);
        }

        // reduce across K-halves via smem (alias over x_sh)
        float* red = (float*)x_sh;               // 4KB <= 16KB
        __syncthreads();
        if (kh == 1) {
            #pragma unroll
            for (int r = 0; r < 4; r++) {
                red[((ng * 2 + 0) * 32 + lane) * 4 + r] = c0[r];
                red[((ng * 2 + 1) * 32 + lane) * 4 + r] = c1[r];
            }
        }
        __syncthreads();
        if (kh == 0) {
            #pragma unroll
            for (int r = 0; r < 4; r++) {
                c0[r] += red[((ng * 2 + 0) * 32 + lane) * 4 + r];
                c1[r] += red[((ng * 2 + 1) * 32 + lane) * 4 + r];
            }
            int r0 = base + (lane >> 2);
            int r1 = r0 + 8;
            int col0 = (ng * 2 + 0) * 8 + (lane & 3) * 2;
            int col1 = (ng * 2 + 1) * 8 + (lane & 3) * 2;
            if (r0 < N) {
                *(float2*)&out[(long long)r0 * COUT + col0] = make_float2(c0[0], c0[1]);
                *(float2*)&out[(long long)r0 * COUT + col1] = make_float2(c1[0], c1[1]);
            }
            if (r1 < N) {
                *(float2*)&out[(long long)r1 * COUT + col0] = make_float2(c0[2], c0[3]);
                *(float2*)&out[(long long)r1 * COUT + col1] = make_float2(c1[2], c1[3]);
            }
        }
    }
}

extern "C" void kernel_launch(void* const* d_in, const int* in_sizes, int n_in,
                              void* d_out, int out_size) {
    const float* q_pts     = (const float*)d_in[0];
    const float* neighbors = (const float*)d_in[2];
    const float* x         = (const float*)d_in[4];
    const float* kp        = (const float*)d_in[5];
    const float* W         = (const float*)d_in[6];
    float* out = (float*)d_out;

    int N = in_sizes[0] / 3;

    cudaFuncSetAttribute(kpconv_kernel,
                         cudaFuncAttributeMaxDynamicSharedMemorySize, SMEM_TOTAL);

    pack_bfrag<<<(8 * NKS * 32 + 255) / 256, 256>>>(W);
    int grid = (N + PBLK - 1) / PBLK;
    kpconv_kernel<<<grid, THREADS, SMEM_TOTAL>>>(q_pts, neighbors, x, kp, out, N);
}